// round 6
// baseline (speedup 1.0000x reference)
#include <cuda_runtime.h>
#include <cuda_bf16.h>
#include <math.h>
#include <stdint.h>

#define T_LEN   3000
#define C_CH    1024
#define B_SZ    16
#define KSIZE   24
#define THREADS 256
#define SEG     750
#define NSEG    4
#define NTILE   47       // ceil(SEG/16); tile 46 store-masked to the segment
#define XSTRIDE 808      // u16 row stride: 404 words, 404%32=20 -> rows on distinct banks
#define XCOUNT  784      // staged elems/row: offsets 0..783 <-> x[750*seg-23 .. 750*seg+760]

// mma.sync m16n8k16 bf16 (baseline PTX, lowers to HMMA on sm_103 non-'a' target)
__device__ __forceinline__ void mma_bf16(float& d0, float& d1, float& d2, float& d3,
                                         uint32_t a0, uint32_t a1, uint32_t a2, uint32_t a3,
                                         uint32_t b0, uint32_t b1) {
    asm volatile(
        "mma.sync.aligned.m16n8k16.row.col.f32.bf16.bf16.f32 "
        "{%0,%1,%2,%3}, {%4,%5,%6,%7}, {%8,%9}, {%0,%1,%2,%3};"
        : "+f"(d0), "+f"(d1), "+f"(d2), "+f"(d3)
        : "r"(a0), "r"(a1), "r"(a2), "r"(a3), "r"(b0), "r"(b1));
}

__device__ __forceinline__ void split_bf16(float v, unsigned short& h, unsigned short& l) {
    __nv_bfloat16 hb = __float2bfloat16(v);
    h = __bfloat16_as_ushort(hb);
    l = __bfloat16_as_ushort(__float2bfloat16(v - __bfloat162float(hb)));
}

__global__ void __launch_bounds__(THREADS)
ssm_hmma_kernel(const float* __restrict__ x, const float* __restrict__ alpha,
                const float* __restrict__ beta, const float* __restrict__ theta,
                float* __restrict__ y)
{
    __shared__ float wf[KSIZE];
    __shared__ unsigned short wh16[72], wl16[72];      // wval(j) at index j+16, zero-padded
    __shared__ __align__(16) unsigned short xh[8][XSTRIDE];
    __shared__ __align__(16) unsigned short xl[8][XSTRIDE];

    const int tid  = threadIdx.x;
    const int c    = blockIdx.x & (C_CH - 1);
    const int rest = blockIdx.x >> 10;
    const int bg   = rest & 1;                 // batch group (8 rows)
    const int seg  = rest >> 1;                // T segment 0..3
    const int segBase = seg * SEG;

    // Per-channel taps: w[k] = beta * exp(log(max(alpha,1e-6))*k) * cos_approx(theta*k)
    if (tid < KSIZE) {
        float a  = fmaxf(alpha[c], 1e-6f);
        float k  = (float)tid;
        float xx = theta[c] * k;
        float x2 = xx * xx;
        float ph = 1.0f - 0.5f * x2 + (x2 * x2) * (1.0f / 24.0f);
        wf[tid]  = beta[c] * expf(logf(a) * k) * ph;
    }
    __syncthreads();

    // Banded weight buffer split to bf16 hi/lo: index j+16 holds wval(j).
    if (tid < 72) {
        int j = tid - 16;
        float v = (j >= 0 && j < KSIZE) ? wf[j] : 0.0f;
        split_bf16(v, wh16[tid], wl16[tid]);
    }

    // Stage x segment for 8 batch rows (hi/lo bf16), coalesced, zero-padded.
    #pragma unroll
    for (int r = 0; r < 8; r++) {
        const float* xr = x + (size_t)((bg * 8 + r) * C_CH + c) * T_LEN;
        for (int off = tid; off < XCOUNT; off += THREADS) {
            int t = segBase - 23 + off;
            float v = (t >= 0 && t < T_LEN) ? __ldg(xr + t) : 0.0f;
            split_bf16(v, xh[r][off], xl[r][off]);
        }
    }
    __syncthreads();

    const int lane = tid & 31;
    const int wrp  = tid >> 5;
    const int g    = lane >> 2;     // groupID
    const int t4   = lane & 3;      // thread-in-group

    // Toeplitz A fragments, built once: Q[m] = pack(wval(jb+8m-8), wval(jb+8m-7)),
    // jb = 2*t4 - g. Then a0(s)=Q[2s+1], a1(s)=Q[2s], a2(s)=Q[2s+2], a3(s)=a0(s).
    uint32_t Qh[7], Ql[7];
    {
        const int base = 2 * t4 - g + 8;    // buffer index of Q[0] (= jb-8+16)
        #pragma unroll
        for (int m = 0; m < 7; m++) {
            int idx = base + 8 * m;
            Qh[m] = (uint32_t)wh16[idx] | ((uint32_t)wh16[idx + 1] << 16);
            Ql[m] = (uint32_t)wl16[idx] | ((uint32_t)wl16[idx + 1] << 16);
        }
    }

    const int segEnd = segBase + SEG;
    float* y0 = y + (size_t)((bg * 8 + 2 * t4) * C_CH + c) * T_LEN;
    float* y1 = y0 + (size_t)C_CH * T_LEN;

    // Each warp: tiles wrp, wrp+8, ... (16 outputs x 8 batch rows per tile).
    for (int tile = wrp; tile < NTILE; tile += 8) {
        const int t0 = 16 * tile;
        float d0 = 0.f, d1 = 0.f, d2 = 0.f, d3 = 0.f;

        #pragma unroll
        for (int s = 0; s < 3; s++) {
            const int off = t0 + 2 * t4 + 16 * s;          // even -> 4B aligned
            uint32_t bh0 = *(const uint32_t*)&xh[g][off];
            uint32_t bh1 = *(const uint32_t*)&xh[g][off + 8];
            uint32_t bl0 = *(const uint32_t*)&xl[g][off];
            uint32_t bl1 = *(const uint32_t*)&xl[g][off + 8];

            uint32_t a0 = Qh[2*s + 1], a1 = Qh[2*s], a2 = Qh[2*s + 2];
            mma_bf16(d0, d1, d2, d3, a0, a1, a2, a0, bh0, bh1);   // Wh * Xh
            mma_bf16(d0, d1, d2, d3, a0, a1, a2, a0, bl0, bl1);   // Wh * Xl
            mma_bf16(d0, d1, d2, d3,
                     Ql[2*s + 1], Ql[2*s], Ql[2*s + 2], Ql[2*s + 1],
                     bh0, bh1);                                   // Wl * Xh
        }

        // D[i,b]: thread holds outputs (t0+g, t0+g+8) for batches (2*t4, 2*t4+1).
        const int tg0 = segBase + t0 + g;
        const int tg2 = tg0 + 8;
        if (tg0 < segEnd) { y0[tg0] = d0; y1[tg0] = d1; }
        if (tg2 < segEnd) { y0[tg2] = d2; y1[tg2] = d3; }
    }
}

extern "C" void kernel_launch(void* const* d_in, const int* in_sizes, int n_in,
                              void* d_out, int out_size)
{
    const float* x     = (const float*)d_in[0];
    const float* alpha = (const float*)d_in[1];
    const float* beta  = (const float*)d_in[2];
    const float* theta = (const float*)d_in[3];
    float* y = (float*)d_out;

    const int grid = NSEG * 2 * C_CH;   // 8192 CTAs
    ssm_hmma_kernel<<<grid, THREADS>>>(x, alpha, beta, theta, y);
}

// round 7
// speedup vs baseline: 1.0942x; 1.0942x over previous
#include <cuda_runtime.h>
#include <cuda_bf16.h>
#include <math.h>
#include <stdint.h>

#define T_LEN   3000
#define C_CH    1024
#define B_SZ    16
#define KSIZE   24
#define THREADS 256
#define SEG     750
#define NSEG    4
#define NTILE   47       // ceil(SEG/16); tile 46 store-masked to the segment
#define XSTRIDE 808      // u16 row stride: 404 words, 404%32=20 -> rows on distinct banks
#define XCOUNT  784      // staged elems/row: offsets 0..783 <-> x[750*seg-23 .. 750*seg+760]

// mma.sync m16n8k16 bf16 (baseline PTX -> HMMA on the harness's compute_103 target)
__device__ __forceinline__ void mma_bf16(float& d0, float& d1, float& d2, float& d3,
                                         uint32_t a0, uint32_t a1, uint32_t a2, uint32_t a3,
                                         uint32_t b0, uint32_t b1) {
    asm volatile(
        "mma.sync.aligned.m16n8k16.row.col.f32.bf16.bf16.f32 "
        "{%0,%1,%2,%3}, {%4,%5,%6,%7}, {%8,%9}, {%0,%1,%2,%3};"
        : "+f"(d0), "+f"(d1), "+f"(d2), "+f"(d3)
        : "r"(a0), "r"(a1), "r"(a2), "r"(a3), "r"(b0), "r"(b1));
}

__device__ __forceinline__ void split_bf16(float v, unsigned short& h, unsigned short& l) {
    __nv_bfloat16 hb = __float2bfloat16(v);
    h = __bfloat16_as_ushort(hb);
    l = __bfloat16_as_ushort(__float2bfloat16(v - __bfloat162float(hb)));
}

__global__ void __launch_bounds__(THREADS)
ssm_hmma_kernel(const float* __restrict__ x, const float* __restrict__ alpha,
                const float* __restrict__ beta, const float* __restrict__ theta,
                float* __restrict__ y)
{
    __shared__ float wf[KSIZE];
    __shared__ unsigned short wh16[72], wl16[72];      // wval(j) at index j+16, zero-padded
    __shared__ __align__(16) unsigned short xh[8][XSTRIDE];
    __shared__ __align__(16) unsigned short xl[8][XSTRIDE];

    const int tid  = threadIdx.x;
    const int c    = blockIdx.x & (C_CH - 1);
    const int rest = blockIdx.x >> 10;
    const int bg   = rest & 1;                 // batch group (8 rows)
    const int seg  = rest >> 1;                // T segment 0..3
    const int segBase = seg * SEG;

    // Per-channel taps: w[k] = beta * exp(log(max(alpha,1e-6))*k) * cos_approx(theta*k)
    if (tid < KSIZE) {
        float a  = fmaxf(alpha[c], 1e-6f);
        float k  = (float)tid;
        float xx = theta[c] * k;
        float x2 = xx * xx;
        float ph = 1.0f - 0.5f * x2 + (x2 * x2) * (1.0f / 24.0f);
        wf[tid]  = beta[c] * expf(logf(a) * k) * ph;
    }
    __syncthreads();

    // Banded weight buffer split to bf16 hi/lo: index j+16 holds wval(j).
    if (tid < 72) {
        int j = tid - 16;
        float v = (j >= 0 && j < KSIZE) ? wf[j] : 0.0f;
        split_bf16(v, wh16[tid], wl16[tid]);
    }

    // Stage x segment for 8 batch rows (hi/lo bf16), coalesced; pack pairs so
    // every smem store is a 4B STS instead of two 2B STS.
    #pragma unroll
    for (int r = 0; r < 8; r++) {
        const float* xr = x + (size_t)((bg * 8 + r) * C_CH + c) * T_LEN;
        for (int p = tid; p < XCOUNT / 2; p += THREADS) {
            int off = 2 * p;
            int t   = segBase - 23 + off;
            float v0 = (t     >= 0 && t     < T_LEN) ? __ldg(xr + t)     : 0.0f;
            float v1 = (t + 1 >= 0 && t + 1 < T_LEN) ? __ldg(xr + t + 1) : 0.0f;
            unsigned short h0, l0, h1, l1;
            split_bf16(v0, h0, l0);
            split_bf16(v1, h1, l1);
            *(uint32_t*)&xh[r][off] = (uint32_t)h0 | ((uint32_t)h1 << 16);
            *(uint32_t*)&xl[r][off] = (uint32_t)l0 | ((uint32_t)l1 << 16);
        }
    }
    __syncthreads();

    const int lane = tid & 31;
    const int wrp  = tid >> 5;
    const int g    = lane >> 2;     // groupID
    const int t4   = lane & 3;      // thread-in-group

    // Toeplitz A fragments, built once: Q[m] = pack(wval(jb+8m-8), wval(jb+8m-7)),
    // jb = 2*t4 - g. Then a0(s)=Q[2s+1], a1(s)=Q[2s], a2(s)=Q[2s+2], a3(s)=a0(s).
    uint32_t Qh[7], Ql[7];
    {
        const int base = 2 * t4 - g + 8;    // buffer index of Q[0] (= jb-8+16)
        #pragma unroll
        for (int m = 0; m < 7; m++) {
            int idx = base + 8 * m;
            Qh[m] = (uint32_t)wh16[idx] | ((uint32_t)wh16[idx + 1] << 16);
            Ql[m] = (uint32_t)wl16[idx] | ((uint32_t)wl16[idx + 1] << 16);
        }
    }

    const int segEnd = segBase + SEG;
    float* y0 = y + (size_t)((bg * 8 + 2 * t4) * C_CH + c) * T_LEN;
    float* y1 = y0 + (size_t)C_CH * T_LEN;

    // Each warp: tiles wrp, wrp+8, ... Three independent accumulator sets per
    // tile (one per precision pass) cut the MMA dependency chain from 9 to 3;
    // unroll-2 over tiles gives 6 concurrent chains per warp.
    #pragma unroll 2
    for (int tile = wrp; tile < NTILE; tile += 8) {
        const int t0 = 16 * tile;
        float p0 = 0.f, p1 = 0.f, p2 = 0.f, p3 = 0.f;   // Wh * Xh
        float q0 = 0.f, q1 = 0.f, q2 = 0.f, q3 = 0.f;   // Wh * Xl
        float r0 = 0.f, r1 = 0.f, r2 = 0.f, r3 = 0.f;   // Wl * Xh

        #pragma unroll
        for (int s = 0; s < 3; s++) {
            const int off = t0 + 2 * t4 + 16 * s;          // even -> 4B aligned
            uint32_t bh0 = *(const uint32_t*)&xh[g][off];
            uint32_t bh1 = *(const uint32_t*)&xh[g][off + 8];
            uint32_t bl0 = *(const uint32_t*)&xl[g][off];
            uint32_t bl1 = *(const uint32_t*)&xl[g][off + 8];

            uint32_t a0 = Qh[2*s + 1], a1 = Qh[2*s], a2 = Qh[2*s + 2];
            mma_bf16(p0, p1, p2, p3, a0, a1, a2, a0, bh0, bh1);
            mma_bf16(q0, q1, q2, q3, a0, a1, a2, a0, bl0, bl1);
            mma_bf16(r0, r1, r2, r3,
                     Ql[2*s + 1], Ql[2*s], Ql[2*s + 2], Ql[2*s + 1],
                     bh0, bh1);
        }

        const float d0 = p0 + q0 + r0;
        const float d1 = p1 + q1 + r1;
        const float d2 = p2 + q2 + r2;
        const float d3 = p3 + q3 + r3;

        // D[i,b]: thread holds outputs (t0+g, t0+g+8) for batches (2*t4, 2*t4+1).
        const int tg0 = segBase + t0 + g;
        const int tg2 = tg0 + 8;
        if (tg0 < segEnd) { y0[tg0] = d0; y1[tg0] = d1; }
        if (tg2 < segEnd) { y0[tg2] = d2; y1[tg2] = d3; }
    }
}

extern "C" void kernel_launch(void* const* d_in, const int* in_sizes, int n_in,
                              void* d_out, int out_size)
{
    const float* x     = (const float*)d_in[0];
    const float* alpha = (const float*)d_in[1];
    const float* beta  = (const float*)d_in[2];
    const float* theta = (const float*)d_in[3];
    float* y = (float*)d_out;

    const int grid = NSEG * 2 * C_CH;   // 8192 CTAs
    ssm_hmma_kernel<<<grid, THREADS>>>(x, alpha, beta, theta, y);
}

// round 8
// speedup vs baseline: 2.5795x; 2.3575x over previous
#include <cuda_runtime.h>
#include <math.h>

#define T_LEN    3000
#define C_CH     1024
#define KSIZE    24
#define HALO     (KSIZE - 1)   // 23
#define SEG      1500          // outputs per CTA (half a row)
#define THREADS  128
#define NGROUP   (SEG / 4)     // 375 groups of 4 consecutive outputs

// s[i] = x_seg[i - 23]; outputs j use s[j..j+23]; group g reads s[4g..4g+27]
// (7x LDS.128). Max touched: s[4*374+27] = s[1523]. Pad to 1536.
#define SBUF_LEN 1536          // 6144 B

__global__ __launch_bounds__(THREADS, 12)
void ssm4d_conv_kernel(const float* __restrict__ x,
                       const float* __restrict__ alpha,
                       const float* __restrict__ beta,
                       const float* __restrict__ theta,
                       float* __restrict__ y)
{
    __shared__ __align__(16) float s[SBUF_LEN];
    __shared__ float wsh[KSIZE];

    const int row  = blockIdx.x >> 1;        // row = b*C + c
    const int half = blockIdx.x & 1;
    const int c    = row & (C_CH - 1);
    const int tid  = threadIdx.x;

    const float* __restrict__ xseg = x + (size_t)row * T_LEN + half * SEG;
    float* __restrict__       yseg = y + (size_t)row * T_LEN + half * SEG;

    // Halo: first half of the row gets zeros; second half gets real data.
    if (tid < HALO)
        s[tid] = half ? xseg[tid - HALO] : 0.0f;
    // Tail pad s[1523..1535] (last group over-reads one unused element).
    if (tid >= HALO && tid < HALO + 13)
        s[SEG + tid] = 0.0f;

    // Synthesize the 24 depthwise taps for this channel (once per block).
    // w[k] = beta * exp(log(max(alpha,1e-6))*k) * (1 - (theta*k)^2/2 + (theta*k)^4/24)
    if (tid < KSIZE) {
        float a   = fmaxf(alpha[c], 1e-6f);
        float la  = logf(a);
        float k   = (float)tid;
        float dec = expf(la * k);
        float xx  = theta[c] * k;
        float x2  = xx * xx;
        float ph  = 1.0f - 0.5f * x2 + (x2 * x2) * (1.0f / 24.0f);
        wsh[tid]  = beta[c] * dec * ph;
    }

    // Stage the segment, coalesced.
    #pragma unroll
    for (int i = tid; i < SEG; i += THREADS)
        s[HALO + i] = xseg[i];

    __syncthreads();

    // Weights to registers (LDS broadcast, conflict-free).
    float w[KSIZE];
    #pragma unroll
    for (int k = 0; k < KSIZE; k++) w[k] = wsh[k];

    // Each thread handles groups g = tid, tid+128, tid+256 (g < 375).
    // Group g = 4 consecutive outputs [4g..4g+3]; lanes 16B apart -> every
    // LDS.128 is a contiguous conflict-free 512B warp access; stores are
    // perfectly coalesced 512B warp STG.128.
    //
    // Chunk-consume: each float4 chunk is folded into the 4 accumulators
    // immediately, keeping only 4 window values live (regs ~32 core ->
    // 12 CTAs/SM resident instead of 9).
    #pragma unroll
    for (int gi = 0; gi < 3; gi++) {
        const int g = tid + gi * THREADS;
        if (g < NGROUP) {
            const float* sp = &s[4 * g];

            float a0 = 0.f, a1 = 0.f, a2 = 0.f, a3 = 0.f;
            #pragma unroll
            for (int q = 0; q < 7; q++) {
                float4 v = *reinterpret_cast<const float4*>(sp + 4 * q);
                #pragma unroll
                for (int i = 0; i < 4; i++) {
                    const int m = 4 * q + i;            // window index
                    const float xv = (i == 0) ? v.x : (i == 1) ? v.y
                                   : (i == 2) ? v.z : v.w;
                    // acc j uses tap k = m - j, valid for 0 <= k < 24.
                    if (m - 0 >= 0 && m - 0 < KSIZE) a0 = fmaf(w[m - 0], xv, a0);
                    if (m - 1 >= 0 && m - 1 < KSIZE) a1 = fmaf(w[m - 1], xv, a1);
                    if (m - 2 >= 0 && m - 2 < KSIZE) a2 = fmaf(w[m - 2], xv, a2);
                    if (m - 3 >= 0 && m - 3 < KSIZE) a3 = fmaf(w[m - 3], xv, a3);
                }
            }

            *reinterpret_cast<float4*>(&yseg[4 * g]) =
                make_float4(a0, a1, a2, a3);
        }
    }
}

extern "C" void kernel_launch(void* const* d_in, const int* in_sizes, int n_in,
                              void* d_out, int out_size)
{
    const float* x     = (const float*)d_in[0];
    const float* alpha = (const float*)d_in[1];
    const float* beta  = (const float*)d_in[2];
    const float* theta = (const float*)d_in[3];
    float* y = (float*)d_out;

    const int rows = in_sizes[0] / T_LEN;   // B*C = 16384
    ssm4d_conv_kernel<<<rows * 2, THREADS>>>(x, alpha, beta, theta, y);
}